// round 7
// baseline (speedup 1.0000x reference)
#include <cuda_runtime.h>
#include <cuda_fp16.h>
#include <cstdint>

#define KDIM 1024
#define IDIM 64
#define ODIM 1024
#define THREADS 288            // 8 consumer warps + 1 producer warp
#define KC 32                  // fp32 k per chunk
#define NCHUNK (KDIM / KC)     // 32
#define NSTAGE 4

#define ROWB 80                // fp16 row: 64B data + 16B pad (conflict-free LDSM)
#define TILE_A (128 * ROWB)    // 10240
#define STAGE_SZ (2 * TILE_A)  // 20480: A tile then B tile
#define OFF_MBAR (NSTAGE * STAGE_SZ)   // 81920; full[s]=+s*16, empty[s]=+s*16+8
#define SMEM_DYN (OFF_MBAR + NSTAGE * 16)

static __device__ __forceinline__ uint32_t smem_u32(const void* p) {
    uint32_t a;
    asm("{ .reg .u64 t; cvta.to.shared.u64 t, %1; cvt.u32.u64 %0, t; }"
        : "=r"(a) : "l"(p));
    return a;
}

static __device__ __forceinline__ void ldm_x4(uint32_t* r, uint32_t addr) {
    asm volatile(
        "ldmatrix.sync.aligned.m8n8.x4.shared.b16 {%0,%1,%2,%3}, [%4];"
        : "=r"(r[0]), "=r"(r[1]), "=r"(r[2]), "=r"(r[3]) : "r"(addr));
}

static __device__ __forceinline__ void mma_f16(float* d, const uint32_t* a,
                                               const uint32_t* b) {
    asm volatile(
        "mma.sync.aligned.m16n8k16.row.col.f32.f16.f16.f32 "
        "{%0,%1,%2,%3}, {%4,%5,%6,%7}, {%8,%9}, {%0,%1,%2,%3};"
        : "+f"(d[0]), "+f"(d[1]), "+f"(d[2]), "+f"(d[3])
        : "r"(a[0]), "r"(a[1]), "r"(a[2]), "r"(a[3]), "r"(b[0]), "r"(b[1]));
}

static __device__ __forceinline__ void mbar_wait(uint32_t mbar, uint32_t parity) {
    asm volatile(
        "{\n\t"
        ".reg .pred P1;\n\t"
        "WL%=:\n\t"
        "mbarrier.try_wait.parity.acquire.cta.shared::cta.b64 P1, [%0], %1, 0x989680;\n\t"
        "@P1 bra.uni WD%=;\n\t"
        "bra.uni WL%=;\n\t"
        "WD%=:\n\t"
        "}"
        :: "r"(mbar), "r"(parity) : "memory");
}

static __device__ __forceinline__ void mbar_arrive(uint32_t mbar) {
    asm volatile("mbarrier.arrive.shared.b64 _, [%0];" :: "r"(mbar) : "memory");
}

static __device__ __forceinline__ uint2 pack_hi4(const float4 v) {
    __half h0 = __float2half_rn(v.x), h1 = __float2half_rn(v.y);
    __half h2 = __float2half_rn(v.z), h3 = __float2half_rn(v.w);
    uint2 r;
    r.x = (uint32_t)__half_as_ushort(h0) | ((uint32_t)__half_as_ushort(h1) << 16);
    r.y = (uint32_t)__half_as_ushort(h2) | ((uint32_t)__half_as_ushort(h3) << 16);
    return r;
}

// Producer batch helpers. Batch b (0..7): b<4 => A tile, else B tile.
// float4 index fl = (b&3)*256 + j*32 + lane, fl in 0..1023 within the tile.
#define PLOAD(buf, b, ga, gb, lane)                                            \
    do {                                                                       \
        const float* gbase_ = ((b) < 4) ? (ga) : (gb);                         \
        _Pragma("unroll") for (int j_ = 0; j_ < 8; ++j_) {                     \
            int fl_ = ((b) & 3) * 256 + j_ * 32 + (lane);                      \
            int row_ = fl_ >> 3, c4_ = fl_ & 7;                                \
            (buf)[j_] = *reinterpret_cast<const float4*>(                      \
                gbase_ + (size_t)row_ * 65536 + c4_ * 4);                      \
        }                                                                      \
    } while (0)

#define PSTORE(buf, b, sm, stg_off, lane)                                      \
    do {                                                                       \
        uint32_t tb_ = ((b) < 4) ? 0u : (uint32_t)TILE_A;                      \
        _Pragma("unroll") for (int j_ = 0; j_ < 8; ++j_) {                     \
            int fl_ = ((b) & 3) * 256 + j_ * 32 + (lane);                      \
            int row_ = fl_ >> 3, c4_ = fl_ & 7;                                \
            *reinterpret_cast<uint2*>((sm) + (stg_off) + tb_ +                 \
                                      row_ * ROWB + c4_ * 8) =                 \
                pack_hi4((buf)[j_]);                                           \
        }                                                                      \
    } while (0)

__global__ void __launch_bounds__(THREADS, 2)
fl_kernel(const float* __restrict__ x, const float* __restrict__ w,
          const float* __restrict__ bias, float* __restrict__ out) {
    extern __shared__ char sm[];
    const uint32_t sbase = smem_u32(sm);
    const int tid = threadIdx.x;
    const int wid = tid >> 5;
    const int lid = tid & 31;
    const int otile = blockIdx.x;  // 0..7
    const int i_idx = blockIdx.y;  // 0..63

    const float* xa = x + (size_t)i_idx * KDIM;
    const float* wa = w + ((size_t)otile * 128) * (IDIM * KDIM) + (size_t)i_idx * KDIM;

    if (tid == 0) {
#pragma unroll
        for (int s = 0; s < NSTAGE; ++s) {
            asm volatile("mbarrier.init.shared.b64 [%0], %1;"
                         :: "r"(sbase + OFF_MBAR + s * 16), "r"(32u) : "memory");
            asm volatile("mbarrier.init.shared.b64 [%0], %1;"
                         :: "r"(sbase + OFF_MBAR + s * 16 + 8), "r"(256u) : "memory");
        }
    }
    __syncthreads();

    if (wid == 8) {
        // ───────────── producer warp ─────────────
#pragma unroll 1
        for (int ch = 0; ch < NCHUNK; ++ch) {
            const int st = ch & (NSTAGE - 1);
            const uint32_t eph = 1u ^ (uint32_t)((ch >> 2) & 1);
            mbar_wait(sbase + OFF_MBAR + st * 16 + 8, eph);

            const uint32_t stg_off = (uint32_t)(st * STAGE_SZ);
            const float* ga = xa + ch * KC;
            const float* gb = wa + ch * KC;
            float4 b0[8], b1[8];
            PLOAD(b0, 0, ga, gb, lid);
            PLOAD(b1, 1, ga, gb, lid); PSTORE(b0, 0, sm, stg_off, lid);
            PLOAD(b0, 2, ga, gb, lid); PSTORE(b1, 1, sm, stg_off, lid);
            PLOAD(b1, 3, ga, gb, lid); PSTORE(b0, 2, sm, stg_off, lid);
            PLOAD(b0, 4, ga, gb, lid); PSTORE(b1, 3, sm, stg_off, lid);
            PLOAD(b1, 5, ga, gb, lid); PSTORE(b0, 4, sm, stg_off, lid);
            PLOAD(b0, 6, ga, gb, lid); PSTORE(b1, 5, sm, stg_off, lid);
            PLOAD(b1, 7, ga, gb, lid); PSTORE(b0, 6, sm, stg_off, lid);
            PSTORE(b1, 7, sm, stg_off, lid);

            mbar_arrive(sbase + OFF_MBAR + st * 16);   // full, count=32
        }
        return;
    }

    // ───────────── consumer warps (wid 0..7) ─────────────
    const int warp_m = wid >> 2;   // 0..1 : 64 M rows each
    const int warp_n = wid & 3;    // 0..3 : 32 N cols each

    float acc[4][4][4];
#pragma unroll
    for (int a = 0; a < 4; ++a)
#pragma unroll
        for (int b = 0; b < 4; ++b)
#pragma unroll
            for (int c = 0; c < 4; ++c) acc[a][b][c] = 0.0f;

    const uint32_t a_row = (uint32_t)(warp_m * 64 + (lid & 15));
    const uint32_t a_cb = (uint32_t)((lid >> 4) * 16);
    const uint32_t b_row = (uint32_t)(warp_n * 32 + ((lid >> 4) << 3) + (lid & 7));
    const uint32_t b_cb = (uint32_t)(((lid >> 3) & 1) * 16);

#pragma unroll 1
    for (int ch = 0; ch < NCHUNK; ++ch) {
        const int st = ch & (NSTAGE - 1);
        mbar_wait(sbase + OFF_MBAR + st * 16, (uint32_t)((ch >> 2) & 1));

        const uint32_t buf = sbase + (uint32_t)(st * STAGE_SZ);
#pragma unroll
        for (int ks = 0; ks < 2; ++ks) {
            uint32_t ah[4][4], bh[2][4];
#pragma unroll
            for (int mt = 0; mt < 4; ++mt)
                ldm_x4(ah[mt], buf + (a_row + mt * 16) * ROWB + ks * 32 + a_cb);
#pragma unroll
            for (int bt = 0; bt < 2; ++bt)
                ldm_x4(bh[bt], buf + TILE_A + (b_row + bt * 16) * ROWB + ks * 32 + b_cb);
#pragma unroll
            for (int mt = 0; mt < 4; ++mt)
#pragma unroll
                for (int nt = 0; nt < 4; ++nt)
                    mma_f16(acc[mt][nt], ah[mt], &bh[nt >> 1][(nt & 1) * 2]);
        }

        mbar_arrive(sbase + OFF_MBAR + st * 16 + 8);   // empty, count=256
    }

    // Epilogue: add bias, store. out[b][o][i] = b*65536 + o*64 + i
    const float* bp = bias + (size_t)(otile * 128) * IDIM + i_idx;
    float bv[4][2];
#pragma unroll
    for (int nt = 0; nt < 4; ++nt) {
        int n_l = warp_n * 32 + nt * 8 + 2 * (lid & 3);
        bv[nt][0] = bp[(size_t)n_l * IDIM];
        bv[nt][1] = bp[(size_t)(n_l + 1) * IDIM];
    }
#pragma unroll
    for (int mt = 0; mt < 4; ++mt) {
        int m0 = warp_m * 64 + mt * 16 + (lid >> 2);
#pragma unroll
        for (int nt = 0; nt < 4; ++nt) {
            int n_l = warp_n * 32 + nt * 8 + 2 * (lid & 3);
            float* o0 = out + (size_t)m0 * (ODIM * IDIM) +
                        (size_t)(otile * 128 + n_l) * IDIM + i_idx;
            o0[0] = acc[mt][nt][0] + bv[nt][0];
            o0[IDIM] = acc[mt][nt][1] + bv[nt][1];
            float* o8 = o0 + (size_t)8 * (ODIM * IDIM);
            o8[0] = acc[mt][nt][2] + bv[nt][0];
            o8[IDIM] = acc[mt][nt][3] + bv[nt][1];
        }
    }
}

extern "C" void kernel_launch(void* const* d_in, const int* in_sizes, int n_in,
                              void* d_out, int out_size) {
    (void)in_sizes; (void)n_in; (void)out_size;
    const float* x = (const float*)d_in[0];
    const float* w = (const float*)d_in[1];
    const float* bias = (const float*)d_in[2];
    float* out = (float*)d_out;

    cudaFuncSetAttribute(fl_kernel, cudaFuncAttributeMaxDynamicSharedMemorySize,
                         SMEM_DYN);
    fl_kernel<<<dim3(ODIM / 128, IDIM), THREADS, SMEM_DYN>>>(x, w, bias, out);
}

// round 8
// speedup vs baseline: 2.1590x; 2.1590x over previous
#include <cuda_runtime.h>
#include <cuda_fp16.h>
#include <cstdint>

#define KDIM 1024
#define IDIM 64
#define ODIM 1024
#define THREADS 256
#define KC 32                  // fp32 k per chunk
#define NCHUNK (KDIM / KC)     // 32

#define ROWB 80                // fp16 tile row: 64B data + 16B pad (conflict-free LDSM)
#define TILE_B (128 * ROWB)    // 10240
#define BUF_SZ (2 * TILE_B)    // 20480: AH, BH (1-term: no lo tiles)
#define T_AH 0
#define T_BH TILE_B

#define OFF_STG (2 * BUF_SZ)       // 40960 (single fp32 stage buffer)
#define STG_B_OFF (128 * KC * 4)   // 16384
#define STG_SZ (2 * 128 * KC * 4)  // 32768 (A + B fp32)
#define SMEM_DYN (OFF_STG + STG_SZ)  // 73728 = 72KB -> 2 CTAs/SM

static __device__ __forceinline__ uint32_t smem_u32(const void* p) {
    uint32_t a;
    asm("{ .reg .u64 t; cvta.to.shared.u64 t, %1; cvt.u32.u64 %0, t; }"
        : "=r"(a) : "l"(p));
    return a;
}

static __device__ __forceinline__ void ldm_x4(uint32_t* r, uint32_t addr) {
    asm volatile(
        "ldmatrix.sync.aligned.m8n8.x4.shared.b16 {%0,%1,%2,%3}, [%4];"
        : "=r"(r[0]), "=r"(r[1]), "=r"(r[2]), "=r"(r[3]) : "r"(addr));
}

static __device__ __forceinline__ void mma_f16(float* d, const uint32_t* a,
                                               const uint32_t* b) {
    asm volatile(
        "mma.sync.aligned.m16n8k16.row.col.f32.f16.f16.f32 "
        "{%0,%1,%2,%3}, {%4,%5,%6,%7}, {%8,%9}, {%0,%1,%2,%3};"
        : "+f"(d[0]), "+f"(d[1]), "+f"(d[2]), "+f"(d[3])
        : "r"(a[0]), "r"(a[1]), "r"(a[2]), "r"(a[3]), "r"(b[0]), "r"(b[1]));
}

static __device__ __forceinline__ void cp16(uint32_t saddr, const void* gaddr) {
    asm volatile("cp.async.cg.shared.global [%0], [%1], 16;"
                 :: "r"(saddr), "l"(gaddr));
}

// Stage one K-chunk: A [128 x 32] f32 + B [128 x 32] f32. Each thread stages the
// exact float4s it later converts (self-consumed, program-ordered).
static __device__ __forceinline__ void stage_chunk(uint32_t stg,
                                                   const float* __restrict__ ga,
                                                   const float* __restrict__ gb) {
    const int tid = threadIdx.x;
#pragma unroll
    for (int it = 0; it < 4; ++it) {
        int f = tid + it * THREADS;     // float4 idx 0..1023
        int row = f >> 3;
        int c4 = f & 7;
        cp16(stg + (uint32_t)(f * 16), ga + (size_t)row * 65536 + c4 * 4);
        cp16(stg + STG_B_OFF + (uint32_t)(f * 16), gb + (size_t)row * 65536 + c4 * 4);
    }
    asm volatile("cp.async.commit_group;" ::: "memory");
}

static __device__ __forceinline__ uint2 pack_hi4(const float4 v) {
    __half h0 = __float2half_rn(v.x), h1 = __float2half_rn(v.y);
    __half h2 = __float2half_rn(v.z), h3 = __float2half_rn(v.w);
    uint2 r;
    r.x = (uint32_t)__half_as_ushort(h0) | ((uint32_t)__half_as_ushort(h1) << 16);
    r.y = (uint32_t)__half_as_ushort(h2) | ((uint32_t)__half_as_ushort(h3) << 16);
    return r;
}

// Convert own staged fp32 -> fp16 hi tiles (A and B, no residuals).
static __device__ __forceinline__ void convert_stage(char* sm, uint32_t buf_off) {
    const int tid = threadIdx.x;
#pragma unroll
    for (int it = 0; it < 4; ++it) {
        int f = tid + it * THREADS;
        int row = f >> 3;
        int c4 = f & 7;
        uint32_t dst = (uint32_t)(row * ROWB + c4 * 8);

        const float4 va = *reinterpret_cast<const float4*>(sm + OFF_STG + f * 16);
        *reinterpret_cast<uint2*>(sm + buf_off + T_AH + dst) = pack_hi4(va);

        const float4 vb = *reinterpret_cast<const float4*>(
            sm + OFF_STG + STG_B_OFF + f * 16);
        *reinterpret_cast<uint2*>(sm + buf_off + T_BH + dst) = pack_hi4(vb);
    }
}

__global__ void __launch_bounds__(THREADS, 2)
fl_kernel(const float* __restrict__ x, const float* __restrict__ w,
          const float* __restrict__ bias, float* __restrict__ out) {
    extern __shared__ char sm[];
    const uint32_t sbase = smem_u32(sm);
    const int tid = threadIdx.x;
    const int wid = tid >> 5;
    const int lid = tid & 31;
    const int warp_m = wid >> 2;   // 0..1 : 64 M rows each
    const int warp_n = wid & 3;    // 0..3 : 32 N cols each
    const int otile = blockIdx.x;  // 0..7
    const int i_idx = blockIdx.y;  // 0..63

    const float* xa = x + (size_t)i_idx * KDIM;
    const float* wa = w + ((size_t)otile * 128) * (IDIM * KDIM) + (size_t)i_idx * KDIM;

    float acc[4][4][4];
#pragma unroll
    for (int a = 0; a < 4; ++a)
#pragma unroll
        for (int b = 0; b < 4; ++b)
#pragma unroll
            for (int c = 0; c < 4; ++c) acc[a][b][c] = 0.0f;

    const uint32_t a_row = (uint32_t)(warp_m * 64 + (lid & 15));
    const uint32_t a_cb = (uint32_t)((lid >> 4) * 16);
    const uint32_t b_row = (uint32_t)(warp_n * 32 + ((lid >> 4) << 3) + (lid & 7));
    const uint32_t b_cb = (uint32_t)(((lid >> 3) & 1) * 16);

    // Prologue: stage chunk 0, convert into buf 0.
    stage_chunk(sbase + OFF_STG, xa, wa);
    asm volatile("cp.async.wait_group 0;" ::: "memory");
    convert_stage(sm, 0);
    __syncthreads();

    for (int ch = 0; ch < NCHUNK; ++ch) {
        // Prefetch chunk ch+1 (stage buffer self-consumed last iteration).
        if (ch + 1 < NCHUNK) {
            stage_chunk(sbase + OFF_STG, xa + (ch + 1) * KC, wa + (ch + 1) * KC);
        } else {
            asm volatile("cp.async.commit_group;" ::: "memory");
        }

        // MMA on buf[ch&1]: single term ah*bh
        const uint32_t buf = (uint32_t)((ch & 1) * BUF_SZ);
#pragma unroll
        for (int ks = 0; ks < 2; ++ks) {
            uint32_t ah[4][4], bh[2][4];
#pragma unroll
            for (int mt = 0; mt < 4; ++mt) {
                uint32_t addr = sbase + buf + T_AH +
                                (a_row + mt * 16) * ROWB + ks * 32 + a_cb;
                ldm_x4(ah[mt], addr);
            }
#pragma unroll
            for (int bt = 0; bt < 2; ++bt) {
                uint32_t addr = sbase + buf + T_BH +
                                (b_row + bt * 16) * ROWB + ks * 32 + b_cb;
                ldm_x4(bh[bt], addr);
            }
#pragma unroll
            for (int mt = 0; mt < 4; ++mt)
#pragma unroll
                for (int nt = 0; nt < 4; ++nt)
                    mma_f16(acc[mt][nt], ah[mt], &bh[nt >> 1][(nt & 1) * 2]);
        }

        // Convert chunk ch+1 into buf[(ch+1)&1] (own staged data only)
        asm volatile("cp.async.wait_group 0;" ::: "memory");
        if (ch + 1 < NCHUNK) {
            convert_stage(sm, (uint32_t)(((ch + 1) & 1) * BUF_SZ));
        }
        __syncthreads();
    }

    // Epilogue: add bias, store. out[b][o][i] = b*65536 + o*64 + i
    const float* bp = bias + (size_t)(otile * 128) * IDIM + i_idx;
    float bv[4][2];
#pragma unroll
    for (int nt = 0; nt < 4; ++nt) {
        int n_l = warp_n * 32 + nt * 8 + 2 * (lid & 3);
        bv[nt][0] = bp[(size_t)n_l * IDIM];
        bv[nt][1] = bp[(size_t)(n_l + 1) * IDIM];
    }
#pragma unroll
    for (int mt = 0; mt < 4; ++mt) {
        int m0 = warp_m * 64 + mt * 16 + (lid >> 2);
#pragma unroll
        for (int nt = 0; nt < 4; ++nt) {
            int n_l = warp_n * 32 + nt * 8 + 2 * (lid & 3);
            float* o0 = out + (size_t)m0 * (ODIM * IDIM) +
                        (size_t)(otile * 128 + n_l) * IDIM + i_idx;
            o0[0] = acc[mt][nt][0] + bv[nt][0];
            o0[IDIM] = acc[mt][nt][1] + bv[nt][1];
            float* o8 = o0 + (size_t)8 * (ODIM * IDIM);
            o8[0] = acc[mt][nt][2] + bv[nt][0];
            o8[IDIM] = acc[mt][nt][3] + bv[nt][1];
        }
    }
}

extern "C" void kernel_launch(void* const* d_in, const int* in_sizes, int n_in,
                              void* d_out, int out_size) {
    (void)in_sizes; (void)n_in; (void)out_size;
    const float* x = (const float*)d_in[0];
    const float* w = (const float*)d_in[1];
    const float* bias = (const float*)d_in[2];
    float* out = (float*)d_out;

    cudaFuncSetAttribute(fl_kernel, cudaFuncAttributeMaxDynamicSharedMemorySize,
                         SMEM_DYN);
    fl_kernel<<<dim3(ODIM / 128, IDIM), THREADS, SMEM_DYN>>>(x, w, bias, out);
}